// round 17
// baseline (speedup 1.0000x reference)
#include <cuda_runtime.h>
#include <cuda_bf16.h>

// STFT: B=16, T=262144, n_fft=2048, hop=512, center reflect pad 1024.
// n_frames = 513, n_bins = 1025. Output [real(16,1025,513); imag(...)] fp32.
//
// 8 frames/CTA (512 thr, 64 thr/frame). 1024-pt complex FFT (real packing):
// stage 1 = in-place DIF radix-8 (stride 128), butterflies paired j=2u,2u+1
// (128-bit gmem/smem); stage 2 = in-place radix-8 on blocks of 128,
// butterflies paired jj=2t,2t+1 within one block (128-bit smem); store phase
// = 16-pt DFT per block of 16 in registers (float4 loads) + rfft unpack via
// shfl.xor(16). 4 smem passes, 2 barriers, 3 sincosf, 32B-run gmem stores.

#define NC        1024
#define SROW      1026      // == 2 (mod 16): float4 phases tile all banks
#define HOP       512
#define PADC      1024
#define T_LEN     262144
#define NFFT      2048
#define NFRAMES   513
#define NBINS     1025
#define NB        16
#define THREADS   512
#define FPB       8
#define NGRP      65
#define PI_F      3.14159265358979323846f
#define C4        0.70710678118654752f
#define C16       0.92387953251129f     // cos(pi/8)
#define S16       0.38268343236509f     // sin(pi/8)
#define C1K       0.99998117528260f     // cos(2*pi/1024)
#define S1K       0.00613588464915f     // sin(2*pi/1024)
#define C128      0.99879545620517f     // cos(2*pi/128)
#define S128      0.04906767432742f     // sin(2*pi/128)

__device__ __forceinline__ float2 cadd(float2 a, float2 b) { return make_float2(a.x + b.x, a.y + b.y); }
__device__ __forceinline__ float2 csub(float2 a, float2 b) { return make_float2(a.x - b.x, a.y - b.y); }
__device__ __forceinline__ float2 cmulc(float2 a, float2 w) {
    return make_float2(a.x * w.x - a.y * w.y, a.x * w.y + a.y * w.x);
}
// a * (c - i*s)
__device__ __forceinline__ float2 cmK(float2 a, float c, float s) {
    return make_float2(a.x * c + a.y * s, a.y * c - a.x * s);
}

__device__ __forceinline__ void fft8(float2* a) {
    float2 e0 = cadd(a[0], a[4]), e1 = cadd(a[1], a[5]);
    float2 e2 = cadd(a[2], a[6]), e3 = cadd(a[3], a[7]);
    float2 o0 = csub(a[0], a[4]), o1 = csub(a[1], a[5]);
    float2 o2 = csub(a[2], a[6]), o3 = csub(a[3], a[7]);
    float2 ee0 = cadd(e0, e2), ee1 = cadd(e1, e3);
    float2 eo0 = csub(e0, e2), eo1 = csub(e1, e3);
    a[0] = cadd(ee0, ee1);
    a[4] = csub(ee0, ee1);
    a[2] = make_float2(eo0.x + eo1.y, eo0.y - eo1.x);
    a[6] = make_float2(eo0.x - eo1.y, eo0.y + eo1.x);
    float2 p1 = make_float2(C4 * (o1.x + o1.y), C4 * (o1.y - o1.x));
    float2 p2 = make_float2(o2.y, -o2.x);
    float2 p3 = make_float2(C4 * (o3.y - o3.x), -C4 * (o3.x + o3.y));
    float2 s0 = cadd(o0, p2), s1 = cadd(p1, p3);
    float2 d0 = csub(o0, p2), d1 = csub(p1, p3);
    a[1] = cadd(s0, s1);
    a[5] = csub(s0, s1);
    a[3] = make_float2(d0.x + d1.y, d0.y - d1.x);
    a[7] = make_float2(d0.x - d1.y, d0.y + d1.x);
}

__device__ __forceinline__ void fft4(float2& a0, float2& a1, float2& a2, float2& a3) {
    float2 t0 = cadd(a0, a2), t1 = csub(a0, a2);
    float2 t2 = cadd(a1, a3), t3 = csub(a1, a3);
    a0 = cadd(t0, t2);
    a2 = csub(t0, t2);
    float2 b1 = make_float2(t1.x + t3.y, t1.y - t3.x);
    float2 b3 = make_float2(t1.x - t3.y, t1.y + t3.x);
    a1 = b1;
    a3 = b3;
}

__device__ __forceinline__ void twiddle8(float2* a, float2 w1) {
    float2 wk = w1;
    a[1] = cmulc(a[1], wk);
#pragma unroll
    for (int r = 2; r < 8; r++) { wk = cmulc(wk, w1); a[r] = cmulc(a[r], wk); }
}

__device__ __forceinline__ void bar_frame(int fl) {
    asm volatile("bar.sync %0, 64;" :: "r"(fl + 1) : "memory");
}

__device__ __forceinline__ float2 shfl16_f2(float2 v) {
    return make_float2(__shfl_xor_sync(0xffffffffu, v.x, 16),
                       __shfl_xor_sync(0xffffffffu, v.y, 16));
}

// X[k] from zk=Z[k], zn=Z[(1024-k)%1024], (cw,sw)=(cos,sin)(pi*k/1024)
__device__ __forceinline__ float2 unpack_one(float2 zk, float2 zn, float cw, float sw) {
    const float er  = 0.5f * (zk.x + zn.x);
    const float ei  = 0.5f * (zk.y - zn.y);
    const float orr = 0.5f * (zk.y + zn.y);
    const float oi  = 0.5f * (zn.x - zk.x);
    return make_float2(er + (orr * cw + oi * sw), ei - (orr * sw - oi * cw));
}

extern __shared__ float2 buf[];   // FPB * SROW float2 = 65,664 B

__global__ __launch_bounds__(THREADS, 2)
void stft_kernel(const float* __restrict__ x,
                 const float* __restrict__ win,
                 float* __restrict__ out) {
    const int g   = blockIdx.x % NGRP;
    const int b   = blockIdx.x / NGRP;
    const int tid = threadIdx.x;
    const int fl  = tid >> 6;
    const int u   = tid & 63;
    const int f   = g * FPB + fl;
    const float* __restrict__ xb = x + (long)b * T_LEN;
    const int base = f * HOP - PADC;
    float2* __restrict__ row = buf + fl * SROW;

    // ---- stage 1: in-place DIF radix-8 (n=1024), paired butterflies
    //      j = 2u, 2u+1 -> all gmem/smem traffic 128-bit ----
    const bool interior = (base >= 0) && (base + NFFT <= T_LEN);
    {
        float2 A[2][8];
        if (interior) {
            const float4* __restrict__ xv4 = (const float4*)(xb + base);
            const float4* __restrict__ wv4 = (const float4*)win;
#pragma unroll
            for (int m = 0; m < 8; m++) {
                const float4 v = xv4[u + (m << 6)];
                const float4 w = wv4[u + (m << 6)];
                A[0][m] = make_float2(v.x * w.x, v.y * w.y);
                A[1][m] = make_float2(v.z * w.z, v.w * w.w);
            }
        } else {
#pragma unroll
            for (int m = 0; m < 8; m++) {
                const int e0 = base + 4 * u + 256 * m;
#pragma unroll
                for (int q = 0; q < 2; q++) {
                    int t0 = e0 + 2 * q;
                    int t1 = e0 + 2 * q + 1;
                    t0 = (t0 < 0) ? -t0 : ((t0 >= T_LEN) ? 2 * T_LEN - 2 - t0 : t0);
                    t1 = (t1 < 0) ? -t1 : ((t1 >= T_LEN) ? 2 * T_LEN - 2 - t1 : t1);
                    const int wbase = 4 * u + 256 * m + 2 * q;
                    A[q][m] = make_float2(xb[t0] * win[wbase],
                                          xb[t1] * win[wbase + 1]);
                }
            }
        }
        float2 Wa;
        {
            float s1, c1;
            __sincosf((float)(2 * u) * (-2.0f * PI_F / 1024.0f), &s1, &c1);
            Wa = make_float2(c1, s1);
        }
        const float2 Wb = cmK(Wa, C1K, S1K);
        fft8(A[0]);
        twiddle8(A[0], Wa);
        fft8(A[1]);
        twiddle8(A[1], Wb);
        float4* __restrict__ r4 = (float4*)row;
#pragma unroll
        for (int m = 0; m < 8; m++)
            r4[u + (m << 6)] = make_float4(A[0][m].x, A[0][m].y,
                                           A[1][m].x, A[1][m].y);
    }
    bar_frame(fl);

    // ---- stage 2: in-place radix-8 on blocks of 128, paired butterflies
    //      jj = 2t, 2t+1 within block blk=u>>3 -> 128-bit smem ----
    {
        const int t   = u & 7;
        const int blk = u >> 3;
        float s1, c1;
        __sincosf((float)(2 * t) * (-2.0f * PI_F / 128.0f), &s1, &c1);
        const float2 Wa = make_float2(c1, s1);
        const float2 Wb = cmK(Wa, C128, S128);
        float4* __restrict__ r4 = (float4*)row;
        const int base4 = (blk << 6) + t;           // float4 idx: 64*blk + t + 8m
        float2 A0[8], A1[8];
#pragma unroll
        for (int m = 0; m < 8; m++) {
            const float4 v = r4[base4 + (m << 3)];
            A0[m] = make_float2(v.x, v.y);
            A1[m] = make_float2(v.z, v.w);
        }
        fft8(A0);
        twiddle8(A0, Wa);
        fft8(A1);
        twiddle8(A1, Wb);
#pragma unroll
        for (int m = 0; m < 8; m++)
            r4[base4 + (m << 3)] = make_float4(A0[m].x, A0[m].y,
                                               A1[m].x, A1[m].y);
    }
    __syncthreads();   // store phase reads other frames

    // ---- store phase: 16-pt DFT per block of 16 in registers + unpack ----
    {
        const int lane = tid & 31;
        const int w    = tid >> 5;          // warp 0..15
        const int fs   = lane & 7;
        const int c    = lane >> 3;         // 0..3
        int kb;
        if (w == 0) kb = (c == 0) ? 0 : (c == 1) ? 1 : (c == 2) ? 32 : 63;
        else {
            const int t2 = w << 1;
            kb = (c == 0) ? t2 : (c == 1) ? t2 + 1 : (c == 2) ? 64 - t2 : 63 - t2;
        }
        const int  fstore = g * FPB + fs;
        const bool valid  = (fstore < NFRAMES);
        const long ro       = ((long)b * NBINS) * NFRAMES + fstore;
        const long imag_off = (long)NB * NBINS * NFRAMES;
        const float4* __restrict__ Zr4 = (const float4*)(buf + fs * SROW);

        const int bblk = (kb >> 3) + ((kb & 7) << 3);   // block of 16
        float2 a[16];
#pragma unroll
        for (int p = 0; p < 8; p++) {
            const float4 v = Zr4[(bblk << 3) + p];
            a[2 * p]     = make_float2(v.x, v.y);
            a[2 * p + 1] = make_float2(v.z, v.w);
        }

        // stage A: DFT4 over m (n = j + 4m), then *= W16^{j*k0}
#pragma unroll
        for (int j = 0; j < 4; j++) fft4(a[j], a[j + 4], a[j + 8], a[j + 12]);
        a[5]  = cmK(a[5],  C16, S16);
        a[9]  = cmK(a[9],  C4,  C4);
        a[13] = cmK(a[13], S16, C16);
        a[6]  = cmK(a[6],  C4,  C4);
        a[10] = make_float2(a[10].y, -a[10].x);
        a[14] = cmK(a[14], -C4, C4);
        a[7]  = cmK(a[7],  S16, C16);
        a[11] = cmK(a[11], -C4, C4);
        a[15] = cmK(a[15], -C16, -S16);
        // stage B: DFT4 over j -> slot 4k0+k1 = Z[kb + 64(k0+4k1)]
#pragma unroll
        for (int k0 = 0; k0 < 4; k0++)
            fft4(a[4 * k0], a[4 * k0 + 1], a[4 * k0 + 2], a[4 * k0 + 3]);

        float ca, sa;
        __sincosf((float)kb * (PI_F / 1024.0f), &sa, &ca);
        const bool self0  = (kb == 0);
        const bool self32 = (kb == 32);

        const float CT[16] = { 1.0f, 0.98078528f, 0.92387953f, 0.83146961f,
                               0.70710678f, 0.55557023f, 0.38268343f, 0.19509032f,
                               0.0f, -0.19509032f, -0.38268343f, -0.55557023f,
                              -0.70710678f, -0.83146961f, -0.92387953f, -0.98078528f };
        const float ST[16] = { 0.0f, 0.19509032f, 0.38268343f, 0.55557023f,
                               0.70710678f, 0.83146961f, 0.92387953f, 0.98078528f,
                               1.0f, 0.98078528f, 0.92387953f, 0.83146961f,
                               0.70710678f, 0.55557023f, 0.38268343f, 0.19509032f };

#pragma unroll
        for (int k1 = 0; k1 < 4; k1++) {
#pragma unroll
            for (int k0 = 0; k0 < 4; k0++) {
                const int s     = k0 + 4 * k1;
                const int slot  = 4 * k0 + k1;
                const int cslot = 4 * (3 - k0) + (3 - k1);
                const float2 sh = shfl16_f2(a[cslot]);
                float2 zn = self32 ? a[cslot] : sh;
                if (self0) {
                    const int sc = (16 - s) & 15;
                    zn = a[4 * (sc & 3) + (sc >> 2)];
                }
                const int k = kb + 64 * s;
                if (self0 && s == 0) {
                    if (valid) {
                        out[ro]            = a[0].x + a[0].y;       // X[0]
                        out[imag_off + ro] = 0.0f;
                        const long oN = ro + (long)NC * NFRAMES;    // X[1024]
                        out[oN]            = a[0].x - a[0].y;
                        out[imag_off + oN] = 0.0f;
                    }
                } else {
                    const float cw = ca * CT[s] - sa * ST[s];
                    const float sw = sa * CT[s] + ca * ST[s];
                    const float2 X = unpack_one(a[slot], zn, cw, sw);
                    if (valid) {
                        const long o = ro + (long)k * NFRAMES;
                        out[o]            = X.x;
                        out[imag_off + o] = X.y;
                    }
                }
            }
        }
    }
}

extern "C" void kernel_launch(void* const* d_in, const int* in_sizes, int n_in,
                              void* d_out, int out_size) {
    const float* x   = (const float*)d_in[0];
    const float* win = (const float*)d_in[1];
    float* out = (float*)d_out;
    const int smem_bytes = FPB * SROW * (int)sizeof(float2);   // 65,664
    cudaFuncSetAttribute(stft_kernel, cudaFuncAttributeMaxDynamicSharedMemorySize,
                         smem_bytes);
    stft_kernel<<<NB * NGRP, THREADS, smem_bytes>>>(x, win, out);
}